// round 1
// baseline (speedup 1.0000x reference)
#include <cuda_runtime.h>
#include <math.h>

// RNNLayer_73074573574765: delayed RNN
//   B=64, S=512, I=1024, H=1024, DELAY=4
// out[b,s,h] then h_final[d,b,h] concatenated in d_out.
//
// Phase 1: pre[m,h] = X[m,:] . Wih[h,:] + bih[h] + bhh[h]   (m = b*S+s)
// Phase 2: 128 sequential groups; group g computes steps t=4g..4g+3:
//          out[b,t,:] = tanh(pre[b,t,:] + hprev . Whh^T)
//          hprev = hidden_state[t] (t<4) else out[b,t-4,:]
// Phase 3: h_final[d] = out[:, S-4+d, :]

namespace {
constexpr int Bz = 64;
constexpr int Sz = 512;
constexpr int Iz = 1024;
constexpr int Hz = 1024;
constexpr int DZ = 4;
}  // namespace

// 128 MB scratch for the precomputed input projection (allowed: static __device__).
__device__ float g_pre[(size_t)Bz * Sz * Hz];

// ---------------------------------------------------------------------------
// Phase 1: C[m,n] = sum_k X[m,k] * Wih[n,k] + bih[n] + bhh[n]
// M=32768, N=1024, K=1024. Tiles: BM=128, BN=128, BK=8, thread tile 8x8.
// ---------------------------------------------------------------------------
__global__ __launch_bounds__(256, 2) void pre_gemm_kernel(
    const float* __restrict__ X, const float* __restrict__ Wih,
    const float* __restrict__ bih, const float* __restrict__ bhh) {
  __shared__ float As[8][128];
  __shared__ float Bs[8][128];

  const int tid = threadIdx.x;
  const int bm = blockIdx.y;
  const int bn = blockIdx.x;

  // loader mapping: 256 threads load 128 rows x 8 k (one float4 each)
  const int lrow = tid >> 1;
  const int lcol = (tid & 1) << 2;
  const float* Ag = X + (size_t)(bm * 128 + lrow) * Iz + lcol;
  const float* Bg = Wih + (size_t)(bn * 128 + lrow) * Iz + lcol;

  // compute mapping: 16x16 thread grid, 8x8 per thread
  const int tr = tid >> 4;
  const int tc = tid & 15;

  float acc[8][8];
#pragma unroll
  for (int i = 0; i < 8; i++)
#pragma unroll
    for (int j = 0; j < 8; j++) acc[i][j] = 0.f;

  for (int k0 = 0; k0 < Iz; k0 += 8) {
    float4 a4 = *reinterpret_cast<const float4*>(Ag + k0);
    float4 b4 = *reinterpret_cast<const float4*>(Bg + k0);
    As[lcol + 0][lrow] = a4.x;
    As[lcol + 1][lrow] = a4.y;
    As[lcol + 2][lrow] = a4.z;
    As[lcol + 3][lrow] = a4.w;
    Bs[lcol + 0][lrow] = b4.x;
    Bs[lcol + 1][lrow] = b4.y;
    Bs[lcol + 2][lrow] = b4.z;
    Bs[lcol + 3][lrow] = b4.w;
    __syncthreads();

#pragma unroll
    for (int k = 0; k < 8; k++) {
      float ra[8], rb[8];
      *reinterpret_cast<float4*>(ra) =
          *reinterpret_cast<const float4*>(&As[k][tr * 8]);
      *reinterpret_cast<float4*>(ra + 4) =
          *reinterpret_cast<const float4*>(&As[k][tr * 8 + 4]);
      *reinterpret_cast<float4*>(rb) =
          *reinterpret_cast<const float4*>(&Bs[k][tc * 8]);
      *reinterpret_cast<float4*>(rb + 4) =
          *reinterpret_cast<const float4*>(&Bs[k][tc * 8 + 4]);
#pragma unroll
      for (int i = 0; i < 8; i++)
#pragma unroll
        for (int j = 0; j < 8; j++) acc[i][j] += ra[i] * rb[j];
    }
    __syncthreads();
  }

  float bias[8];
#pragma unroll
  for (int j = 0; j < 8; j++) {
    int n = bn * 128 + tc * 8 + j;
    bias[j] = bih[n] + bhh[n];
  }

#pragma unroll
  for (int i = 0; i < 8; i++) {
    size_t row = (size_t)(bm * 128 + tr * 8 + i) * Hz;
    size_t col = (size_t)bn * 128 + tc * 8;
#pragma unroll
    for (int j = 0; j < 8; j += 4) {
      float4 v;
      v.x = acc[i][j + 0] + bias[j + 0];
      v.y = acc[i][j + 1] + bias[j + 1];
      v.z = acc[i][j + 2] + bias[j + 2];
      v.w = acc[i][j + 3] + bias[j + 3];
      *reinterpret_cast<float4*>(&g_pre[row + col + j]) = v;
    }
  }
}

// ---------------------------------------------------------------------------
// Phase 2: one group g = 4 independent timesteps. Rows m = d*64 + b (0..255).
// out[b, 4g+d, n] = tanh(pre[b,4g+d,n] + sum_k hprev[m,k] * Whh[n,k])
// Tiles: BM=32, BN=64, BK=16, thread tile 2x4. Grid = 16 x 8 = 128 blocks.
// ---------------------------------------------------------------------------
__global__ __launch_bounds__(256) void rnn_step_kernel(
    const float* __restrict__ hs, const float* __restrict__ Whh,
    float* __restrict__ out, int gstep) {
  __shared__ float As[16][32];
  __shared__ float Bs[16][64];

  const int tid = threadIdx.x;
  const int bn = blockIdx.x;  // 0..15 over N
  const int bm = blockIdx.y;  // 0..7  over M=256

  // A loader: 32 rows x 16 k, one float2 each
  const int arow = tid >> 3;      // 0..31
  const int ak = (tid & 7) << 1;  // 0,2,...,14
  const int m = bm * 32 + arow;
  const int dA = m >> 6;
  const int bA = m & 63;
  const float* hrow;
  if (gstep == 0)
    hrow = hs + (size_t)m * Hz;  // hidden_state is [4,64,H] = [m,H]
  else
    hrow = out + ((size_t)bA * Sz + (4 * gstep + dA - 4)) * Hz;
  hrow += ak;

  // B loader: 64 rows x 16 k, one float4 each
  const int brow = tid >> 2;      // 0..63
  const int bk = (tid & 3) << 2;  // 0,4,8,12
  const float* wrow = Whh + (size_t)(bn * 64 + brow) * Hz + bk;

  // compute mapping: 16x16 thread grid; rows tr*2+{0,1}, cols tc*4+{0..3}
  const int tr = tid >> 4;
  const int tc = tid & 15;

  float acc[2][4] = {{0.f, 0.f, 0.f, 0.f}, {0.f, 0.f, 0.f, 0.f}};

  for (int k0 = 0; k0 < Hz; k0 += 16) {
    float2 a2 = *reinterpret_cast<const float2*>(hrow + k0);
    float4 b4 = *reinterpret_cast<const float4*>(wrow + k0);
    As[ak + 0][arow] = a2.x;
    As[ak + 1][arow] = a2.y;
    Bs[bk + 0][brow] = b4.x;
    Bs[bk + 1][brow] = b4.y;
    Bs[bk + 2][brow] = b4.z;
    Bs[bk + 3][brow] = b4.w;
    __syncthreads();

#pragma unroll
    for (int k = 0; k < 16; k++) {
      float2 ra = *reinterpret_cast<const float2*>(&As[k][tr * 2]);
      float4 rb = *reinterpret_cast<const float4*>(&Bs[k][tc * 4]);
      acc[0][0] += ra.x * rb.x;
      acc[0][1] += ra.x * rb.y;
      acc[0][2] += ra.x * rb.z;
      acc[0][3] += ra.x * rb.w;
      acc[1][0] += ra.y * rb.x;
      acc[1][1] += ra.y * rb.y;
      acc[1][2] += ra.y * rb.z;
      acc[1][3] += ra.y * rb.w;
    }
    __syncthreads();
  }

#pragma unroll
  for (int i = 0; i < 2; i++) {
    int mm = bm * 32 + tr * 2 + i;
    int dd = mm >> 6;
    int bb = mm & 63;
    int t = 4 * gstep + dd;
    size_t base = ((size_t)bb * Sz + t) * Hz + (size_t)bn * 64 + tc * 4;
    float4 pv = *reinterpret_cast<const float4*>(&g_pre[base]);
    float4 ov;
    ov.x = tanhf(pv.x + acc[i][0]);
    ov.y = tanhf(pv.y + acc[i][1]);
    ov.z = tanhf(pv.z + acc[i][2]);
    ov.w = tanhf(pv.w + acc[i][3]);
    *reinterpret_cast<float4*>(&out[base]) = ov;
  }
}

// ---------------------------------------------------------------------------
// Phase 3: h_final[d,b,h] = out[b, S-4+d, h]
// ---------------------------------------------------------------------------
__global__ void final_state_kernel(const float* __restrict__ out,
                                   float* __restrict__ hf) {
  int idx = blockIdx.x * 256 + threadIdx.x;  // total DZ*Bz*Hz = 262144
  int h = idx & (Hz - 1);
  int bd = idx >> 10;
  int b = bd & (Bz - 1);
  int d = bd >> 6;
  hf[idx] = out[((size_t)b * Sz + (Sz - DZ + d)) * Hz + h];
}

extern "C" void kernel_launch(void* const* d_in, const int* in_sizes, int n_in,
                              void* d_out, int out_size) {
  (void)in_sizes;
  (void)n_in;
  (void)out_size;
  const float* X = (const float*)d_in[0];    // [B,S,I]
  const float* hs = (const float*)d_in[1];   // [4,B,H]
  const float* Wih = (const float*)d_in[2];  // [H,I]
  const float* Whh = (const float*)d_in[3];  // [H,H]
  const float* bih = (const float*)d_in[4];  // [H]
  const float* bhh = (const float*)d_in[5];  // [H]

  float* out = (float*)d_out;                      // [B,S,H]
  float* hf = out + (size_t)Bz * Sz * Hz;          // [4,B,H]

  // Phase 1: input projection for all timesteps (one big GEMM)
  pre_gemm_kernel<<<dim3(Hz / 128, (Bz * Sz) / 128), 256>>>(X, Wih, bih, bhh);

  // Phase 2: 128 sequential groups of 4 independent steps
  for (int g = 0; g < Sz / DZ; ++g) {
    rnn_step_kernel<<<dim3(Hz / 64, 256 / 32), 256>>>(hs, Whh, out, g);
  }

  // Phase 3: final hidden-state deque
  final_state_kernel<<<(DZ * Bz * Hz) / 256, 256>>>(out, hf);
}